// round 16
// baseline (speedup 1.0000x reference)
#include <cuda_runtime.h>
#include <cuda_fp16.h>
#include <mma.h>

using namespace nvcuda;

#define N_NODES 50000
#define N_EDGES 800000
#define IN_DIM 128
#define HID_DIM 128
#define N_CLASSES 64
#define PAD_ROWS 64
#define BUCKET 128   // max in-degree slots per node (data mean ~16)

// packed half vectors
struct __align__(8)  h4 { __half2 a, b; };
struct __align__(16) h8 { __half2 a, b, c, d; };

// ---------------- scratch: natively-typed __device__ globals ----------------
// feature tables padded by PAD_ROWS so (a) wmma fragment loads at the ragged
// tail stay in-bounds and (b) row N_NODES is an all-zero SENTINEL row used by
// the aggregation kernels for group padding (device globals are zero-init and
// the pad rows are never written).
__device__ h4      g_hs1[(N_NODES + PAD_ROWS) * 32];  // (x@W1)*dinv[row], fp16
__device__ h4      g_h1 [(N_NODES + PAD_ROWS) * 32];  // relu(agg1), fp16
__device__ __half2 g_hs2[(N_NODES + PAD_ROWS) * 32];  // (h1@W2)*dinv[row], fp16
__device__ h4      g_w1h[128 * 32];                   // W1 fp16 [128x128]
__device__ h4      g_w2h[128 * 16];                   // W2 fp16 [128x64]
__device__ int     g_counts[N_NODES];                 // zero at entry; re-zeroed by k_agg2
__device__ int     g_bucket[N_NODES * BUCKET];        // src lists per dst

// ---------------- ONE-PASS adjacency build + weight fp16 convert ----------------
// edge_index is int32 [2, N_EDGES]: row 0 = src, row 1 = dst
__global__ void k_fill(const int* __restrict__ src, const int* __restrict__ dst,
                       const float* __restrict__ w1, const float* __restrict__ w2) {
    int e = blockIdx.x * blockDim.x + threadIdx.x;
    // fold former k_prep: first threads also convert the weights
    if (e < 128 * 32) {
        float4 v = ((const float4*)w1)[e];
        h4 h;
        h.a = __floats2half2_rn(v.x, v.y);
        h.b = __floats2half2_rn(v.z, v.w);
        g_w1h[e] = h;
    }
    if (e < 128 * 16) {
        float4 v = ((const float4*)w2)[e];
        h4 h;
        h.a = __floats2half2_rn(v.x, v.y);
        h.b = __floats2half2_rn(v.z, v.w);
        g_w2h[e] = h;
    }
    if (e < N_EDGES) {
        int d = dst[e];
        int sv = src[e];
        if (d >= 0 && d < N_NODES && sv >= 0 && sv < N_NODES) {
            int pos = atomicAdd(&g_counts[d], 1);
            if (pos < BUCKET) g_bucket[d * BUCKET + pos] = sv;
        }
    }
}

// ---------------- GEMM layer 1 (tensor cores, fp32 X staged to fp16 smem) ----------------
// g_hs1[r] = fp16( (x[r]@W1) * rsqrt(deg[r]+1) ). Block = 64 rows x 128 cols, 8 warps.
__global__ __launch_bounds__(256) void k_gemm1_tc(const float* __restrict__ X) {
    __shared__ union SM1 {
        __half a[64 * 136];   // 17.4KB, row stride 136 halves = 272B (16B-mult)
        float  c[64 * 128];   // 32KB
    } sm;
    const int tid = threadIdx.x;
    const int wid = tid >> 5;
    const int row0 = blockIdx.x * 64;
    const int mi = wid >> 2;        // 0..1
    const int nj = wid & 3;         // 0..3

    // stage X tile: fp32 global -> fp16 smem (zeros past N_NODES)
    for (int i = tid; i < 64 * 32; i += 256) {
        int r = i >> 5, q = i & 31;
        int gr = row0 + r;
        float4 v = make_float4(0.f, 0.f, 0.f, 0.f);
        if (gr < N_NODES) v = ((const float4*)(X + (size_t)gr * 128))[q];
        __half2* dst = (__half2*)(sm.a + r * 136 + q * 4);
        dst[0] = __floats2half2_rn(v.x, v.y);
        dst[1] = __floats2half2_rn(v.z, v.w);
    }
    __syncthreads();

    wmma::fragment<wmma::accumulator, 16, 16, 16, float> c[2][2];
#pragma unroll
    for (int i = 0; i < 2; i++)
#pragma unroll
        for (int j = 0; j < 2; j++) wmma::fill_fragment(c[i][j], 0.f);

    const __half* B = (const __half*)g_w1h;

    for (int k = 0; k < 128; k += 16) {
        wmma::fragment<wmma::matrix_a, 16, 16, 16, __half, wmma::row_major> a[2];
        wmma::load_matrix_sync(a[0], sm.a + (mi * 32 + 0) * 136 + k, 136);
        wmma::load_matrix_sync(a[1], sm.a + (mi * 32 + 16) * 136 + k, 136);
        wmma::fragment<wmma::matrix_b, 16, 16, 16, __half, wmma::row_major> b[2];
        wmma::load_matrix_sync(b[0], B + k * 128 + nj * 32 + 0, 128);
        wmma::load_matrix_sync(b[1], B + k * 128 + nj * 32 + 16, 128);
#pragma unroll
        for (int i = 0; i < 2; i++)
#pragma unroll
            for (int j = 0; j < 2; j++)
                wmma::mma_sync(c[i][j], a[i], b[j], c[i][j]);
    }
    __syncthreads();   // all warps done reading sm.a before aliasing as sm.c

#pragma unroll
    for (int i = 0; i < 2; i++)
#pragma unroll
        for (int j = 0; j < 2; j++)
            wmma::store_matrix_sync(sm.c + (mi * 32 + i * 16) * 128 + nj * 32 + j * 16,
                                    c[i][j], 128, wmma::mem_row_major);
    __syncthreads();

    // epilogue: scale by rsqrt(deg+1), pack fp16
    for (int i = tid; i < 64 * 32; i += 256) {
        int r = i >> 5, cc = i & 31;
        int gr = row0 + r;
        if (gr < N_NODES) {
            float d = rsqrtf((float)(g_counts[gr] + 1));
            float4 v = *(const float4*)(sm.c + r * 128 + cc * 4);
            h4 h;
            h.a = __floats2half2_rn(v.x * d, v.y * d);
            h.b = __floats2half2_rn(v.z * d, v.w * d);
            g_hs1[(size_t)gr * 32 + cc] = h;
        }
    }
}

// ---------------- GEMM layer 2 (tensor cores): g_hs2[r] = fp16( (g_h1[r]@W2)*dinv[r] ) ----------------
__global__ __launch_bounds__(256) void k_gemm2_tc() {
    __shared__ float Cs[64 * 64];   // 16KB
    const int tid = threadIdx.x;
    const int wid = tid >> 5;
    const int row0 = blockIdx.x * 64;
    const int mi = wid >> 1;        // 0..3
    const int nj2 = wid & 1;        // 0..1

    wmma::fragment<wmma::accumulator, 16, 16, 16, float> c[2];
#pragma unroll
    for (int j = 0; j < 2; j++) wmma::fill_fragment(c[j], 0.f);

    const __half* A = (const __half*)g_h1 + (size_t)row0 * 128;
    const __half* B = (const __half*)g_w2h;

    for (int k = 0; k < 128; k += 16) {
        wmma::fragment<wmma::matrix_a, 16, 16, 16, __half, wmma::row_major> a;
        wmma::load_matrix_sync(a, A + mi * 16 * 128 + k, 128);
        wmma::fragment<wmma::matrix_b, 16, 16, 16, __half, wmma::row_major> b[2];
        wmma::load_matrix_sync(b[0], B + k * 64 + nj2 * 32 + 0, 64);
        wmma::load_matrix_sync(b[1], B + k * 64 + nj2 * 32 + 16, 64);
#pragma unroll
        for (int j = 0; j < 2; j++)
            wmma::mma_sync(c[j], a, b[j], c[j]);
    }

#pragma unroll
    for (int j = 0; j < 2; j++)
        wmma::store_matrix_sync(Cs + mi * 16 * 64 + nj2 * 32 + j * 16,
                                c[j], 64, wmma::mem_row_major);
    __syncthreads();

    for (int i = tid; i < 64 * 32; i += 256) {
        int r = i >> 5, cc = i & 31;
        int gr = row0 + r;
        if (gr < N_NODES) {
            float d = rsqrtf((float)(g_counts[gr] + 1));
            float2 v = *(const float2*)(Cs + r * 64 + cc * 2);
            g_hs2[(size_t)gr * 32 + cc] = __floats2half2_rn(v.x * d, v.y * d);
        }
    }
}

// ---------------- aggregation layer 1: 2 nodes per warp, h8 (16B) lanes ----------------
// Half-warp h owns node = 2*warp+h; lane covers 8 features via one LDG.128.
// Groups of 4 edges per half-warp (8 per warp-instr stream), fp16 tree depth 2,
// fp32 accumulate. Sentinel row N_NODES pads ragged groups.
__global__ __launch_bounds__(256) void k_agg1(const float* __restrict__ bias) {
    __shared__ int sidx[8][32];
    int warp_g = (blockIdx.x * blockDim.x + threadIdx.x) >> 5;  // 0..24999
    int w = threadIdx.x >> 5;
    int lane = threadIdx.x & 31;
    int half = lane >> 4;
    int hl = lane & 15;
    int node = warp_g * 2 + half;            // exact: 3125 blocks * 16 nodes

    int cnt = g_counts[node];
    float d = rsqrtf((float)(cnt + 1));
    int e = min(cnt, BUCKET);
    const int* row = g_bucket + (size_t)node * BUCKET;
    const h8* hv = (const h8*)g_hs1;         // 16 h8 per 256B row

    // self loop (fp32)
    h8 sv = hv[node * 16 + hl];
    float2 fa = __half22float2(sv.a), fb = __half22float2(sv.b);
    float2 fc = __half22float2(sv.c), fd = __half22float2(sv.d);
    float acc[8] = {fa.x, fa.y, fb.x, fb.y, fc.x, fc.y, fd.x, fd.y};

    int eo = __shfl_xor_sync(0xffffffffu, e, 16);
    int emax = max(e, eo);

    for (int base = 0; base < emax; base += 16) {
        int idx = base + hl;
        sidx[w][lane] = (idx < e) ? row[idx] : N_NODES;   // sentinel = zero row
        __syncwarp();
#pragma unroll
        for (int j = 0; j < 16; j += 4) {
            int s0 = sidx[w][(half << 4) | (j + 0)];
            int s1 = sidx[w][(half << 4) | (j + 1)];
            int s2 = sidx[w][(half << 4) | (j + 2)];
            int s3 = sidx[w][(half << 4) | (j + 3)];
            h8 v0 = hv[s0 * 16 + hl];
            h8 v1 = hv[s1 * 16 + hl];
            h8 v2 = hv[s2 * 16 + hl];
            h8 v3 = hv[s3 * 16 + hl];
            __half2 ta = __hadd2(__hadd2(v0.a, v1.a), __hadd2(v2.a, v3.a));
            __half2 tb = __hadd2(__hadd2(v0.b, v1.b), __hadd2(v2.b, v3.b));
            __half2 tc = __hadd2(__hadd2(v0.c, v1.c), __hadd2(v2.c, v3.c));
            __half2 td = __hadd2(__hadd2(v0.d, v1.d), __hadd2(v2.d, v3.d));
            float2 g0 = __half22float2(ta), g1 = __half22float2(tb);
            float2 g2 = __half22float2(tc), g3 = __half22float2(td);
            acc[0] += g0.x; acc[1] += g0.y; acc[2] += g1.x; acc[3] += g1.y;
            acc[4] += g2.x; acc[5] += g2.y; acc[6] += g3.x; acc[7] += g3.y;
        }
        __syncwarp();
    }

    // bias: lane covers features hl*8 .. hl*8+7
    float4 b0 = ((const float4*)bias)[hl * 2 + 0];
    float4 b1 = ((const float4*)bias)[hl * 2 + 1];
    h8 o;
    o.a = __floats2half2_rn(fmaxf(acc[0] * d + b0.x, 0.f), fmaxf(acc[1] * d + b0.y, 0.f));
    o.b = __floats2half2_rn(fmaxf(acc[2] * d + b0.z, 0.f), fmaxf(acc[3] * d + b0.w, 0.f));
    o.c = __floats2half2_rn(fmaxf(acc[4] * d + b1.x, 0.f), fmaxf(acc[5] * d + b1.y, 0.f));
    o.d = __floats2half2_rn(fmaxf(acc[6] * d + b1.z, 0.f), fmaxf(acc[7] * d + b1.w, 0.f));
    ((h8*)g_h1)[node * 16 + hl] = o;
}

// ---------------- aggregation layer 2: 2 nodes per warp, h4 (8B) lanes ----------------
// Also self-cleans g_counts (last consumer) so next call starts from zeros.
__global__ __launch_bounds__(256) void k_agg2(const float* __restrict__ bias,
                                              float* __restrict__ out) {
    __shared__ int sidx[8][32];
    int warp_g = (blockIdx.x * blockDim.x + threadIdx.x) >> 5;
    int w = threadIdx.x >> 5;
    int lane = threadIdx.x & 31;
    int half = lane >> 4;
    int hl = lane & 15;
    int node = warp_g * 2 + half;

    int cnt = g_counts[node];
    float d = rsqrtf((float)(cnt + 1));
    int e = min(cnt, BUCKET);
    const int* row = g_bucket + (size_t)node * BUCKET;
    const h4* hv = (const h4*)g_hs2;         // 16 h4 per 128B row

    // self loop (fp32)
    h4 sv = hv[node * 16 + hl];
    float2 fa = __half22float2(sv.a), fb = __half22float2(sv.b);
    float acc[4] = {fa.x, fa.y, fb.x, fb.y};

    int eo = __shfl_xor_sync(0xffffffffu, e, 16);
    int emax = max(e, eo);

    for (int base = 0; base < emax; base += 16) {
        int idx = base + hl;
        sidx[w][lane] = (idx < e) ? row[idx] : N_NODES;   // sentinel = zero row
        __syncwarp();
#pragma unroll
        for (int j = 0; j < 16; j += 4) {
            int s0 = sidx[w][(half << 4) | (j + 0)];
            int s1 = sidx[w][(half << 4) | (j + 1)];
            int s2 = sidx[w][(half << 4) | (j + 2)];
            int s3 = sidx[w][(half << 4) | (j + 3)];
            h4 v0 = hv[s0 * 16 + hl];
            h4 v1 = hv[s1 * 16 + hl];
            h4 v2 = hv[s2 * 16 + hl];
            h4 v3 = hv[s3 * 16 + hl];
            __half2 ta = __hadd2(__hadd2(v0.a, v1.a), __hadd2(v2.a, v3.a));
            __half2 tb = __hadd2(__hadd2(v0.b, v1.b), __hadd2(v2.b, v3.b));
            float2 g0 = __half22float2(ta), g1 = __half22float2(tb);
            acc[0] += g0.x; acc[1] += g0.y; acc[2] += g1.x; acc[3] += g1.y;
        }
        __syncwarp();
    }

    // bias + output: lane covers cols hl*4 .. hl*4+3 (16B-aligned float4 store)
    float4 b = ((const float4*)bias)[hl];
    float4 o = make_float4(acc[0] * d + b.x, acc[1] * d + b.y,
                           acc[2] * d + b.z, acc[3] * d + b.w);
    ((float4*)out)[node * 16 + hl] = o;

    if (hl == 0) g_counts[node] = 0;         // self-clean for the next call
}

// ---------------- launch: kernel launches ONLY (5 launches) ----------------
extern "C" void kernel_launch(void* const* d_in, const int* in_sizes, int n_in,
                              void* d_out, int out_size) {
    const float* x = (const float*)d_in[0];
    const int* ei = (const int*)d_in[1];   // int32 [2, N_EDGES]
    const float* W1 = (const float*)d_in[2];
    const float* b1 = (const float*)d_in[3];
    const float* W2 = (const float*)d_in[4];
    const float* b2 = (const float*)d_in[5];
    float* out = (float*)d_out;

    const int* esrc = ei;
    const int* edst = ei + N_EDGES;

    k_fill<<<(N_EDGES + 255) / 256, 256>>>(esrc, edst, W1, W2);

    const int gemm_blocks = (N_NODES + 63) / 64;   // 782
    const int agg_blocks = N_NODES / 16;           // 3125 (16 nodes per block)

    // layer 1
    k_gemm1_tc<<<gemm_blocks, 256>>>(x);
    k_agg1<<<agg_blocks, 256>>>(b1);
    // layer 2
    k_gemm2_tc<<<gemm_blocks, 256>>>();
    k_agg2<<<agg_blocks, 256>>>(b2, out);
}

// round 17
// speedup vs baseline: 1.0347x; 1.0347x over previous
#include <cuda_runtime.h>
#include <cuda_fp16.h>
#include <mma.h>

using namespace nvcuda;

#define N_NODES 50000
#define N_EDGES 800000
#define IN_DIM 128
#define HID_DIM 128
#define N_CLASSES 64
#define PAD_ROWS 64
#define BUCKET 128   // max in-degree slots per node (data mean ~16)

// packed half vectors
struct __align__(8)  h4 { __half2 a, b; };
struct __align__(16) h8 { __half2 a, b, c, d; };

// ---------------- scratch: natively-typed __device__ globals ----------------
// feature tables padded by PAD_ROWS so (a) wmma fragment loads at the ragged
// tail stay in-bounds and (b) row N_NODES is an all-zero SENTINEL row used by
// the aggregation kernels for group padding (device globals are zero-init and
// the pad rows are never written).
__device__ h4      g_hs1[(N_NODES + PAD_ROWS) * 32];  // (x@W1)*dinv[row], fp16
__device__ h4      g_h1 [(N_NODES + PAD_ROWS) * 32];  // relu(agg1), fp16
__device__ __half2 g_hs2[(N_NODES + PAD_ROWS) * 32];  // (h1@W2)*dinv[row], fp16
__device__ h4      g_w1h[128 * 32];                   // W1 fp16 [128x128]
__device__ h4      g_w2h[128 * 16];                   // W2 fp16 [128x64]
__device__ int     g_counts[N_NODES];                 // zero at entry; re-zeroed by k_agg2
__device__ int     g_bucket[N_NODES * BUCKET];        // src lists per dst

// ---------------- ONE-PASS adjacency build + weight fp16 convert ----------------
// edge_index is int32 [2, N_EDGES]: row 0 = src, row 1 = dst
__global__ void k_fill(const int* __restrict__ src, const int* __restrict__ dst,
                       const float* __restrict__ w1, const float* __restrict__ w2) {
    int e = blockIdx.x * blockDim.x + threadIdx.x;
    // folded weight convert: first threads also convert W1/W2 to fp16
    if (e < 128 * 32) {
        float4 v = ((const float4*)w1)[e];
        h4 h;
        h.a = __floats2half2_rn(v.x, v.y);
        h.b = __floats2half2_rn(v.z, v.w);
        g_w1h[e] = h;
    }
    if (e < 128 * 16) {
        float4 v = ((const float4*)w2)[e];
        h4 h;
        h.a = __floats2half2_rn(v.x, v.y);
        h.b = __floats2half2_rn(v.z, v.w);
        g_w2h[e] = h;
    }
    if (e < N_EDGES) {
        int d = dst[e];
        int sv = src[e];
        if (d >= 0 && d < N_NODES && sv >= 0 && sv < N_NODES) {
            int pos = atomicAdd(&g_counts[d], 1);
            if (pos < BUCKET) g_bucket[d * BUCKET + pos] = sv;
        }
    }
}

// ---------------- GEMM layer 1 (tensor cores, fp32 X staged to fp16 smem) ----------------
// g_hs1[r] = fp16( (x[r]@W1) * rsqrt(deg[r]+1) ). Block = 64 rows x 128 cols, 8 warps.
__global__ __launch_bounds__(256) void k_gemm1_tc(const float* __restrict__ X) {
    __shared__ union SM1 {
        __half a[64 * 136];   // 17.4KB, row stride 136 halves = 272B (16B-mult)
        float  c[64 * 128];   // 32KB
    } sm;
    const int tid = threadIdx.x;
    const int wid = tid >> 5;
    const int row0 = blockIdx.x * 64;
    const int mi = wid >> 2;        // 0..1
    const int nj = wid & 3;         // 0..3

    // stage X tile: fp32 global -> fp16 smem (zeros past N_NODES)
    for (int i = tid; i < 64 * 32; i += 256) {
        int r = i >> 5, q = i & 31;
        int gr = row0 + r;
        float4 v = make_float4(0.f, 0.f, 0.f, 0.f);
        if (gr < N_NODES) v = ((const float4*)(X + (size_t)gr * 128))[q];
        __half2* dst = (__half2*)(sm.a + r * 136 + q * 4);
        dst[0] = __floats2half2_rn(v.x, v.y);
        dst[1] = __floats2half2_rn(v.z, v.w);
    }
    __syncthreads();

    wmma::fragment<wmma::accumulator, 16, 16, 16, float> c[2][2];
#pragma unroll
    for (int i = 0; i < 2; i++)
#pragma unroll
        for (int j = 0; j < 2; j++) wmma::fill_fragment(c[i][j], 0.f);

    const __half* B = (const __half*)g_w1h;

    for (int k = 0; k < 128; k += 16) {
        wmma::fragment<wmma::matrix_a, 16, 16, 16, __half, wmma::row_major> a[2];
        wmma::load_matrix_sync(a[0], sm.a + (mi * 32 + 0) * 136 + k, 136);
        wmma::load_matrix_sync(a[1], sm.a + (mi * 32 + 16) * 136 + k, 136);
        wmma::fragment<wmma::matrix_b, 16, 16, 16, __half, wmma::row_major> b[2];
        wmma::load_matrix_sync(b[0], B + k * 128 + nj * 32 + 0, 128);
        wmma::load_matrix_sync(b[1], B + k * 128 + nj * 32 + 16, 128);
#pragma unroll
        for (int i = 0; i < 2; i++)
#pragma unroll
            for (int j = 0; j < 2; j++)
                wmma::mma_sync(c[i][j], a[i], b[j], c[i][j]);
    }
    __syncthreads();   // all warps done reading sm.a before aliasing as sm.c

#pragma unroll
    for (int i = 0; i < 2; i++)
#pragma unroll
        for (int j = 0; j < 2; j++)
            wmma::store_matrix_sync(sm.c + (mi * 32 + i * 16) * 128 + nj * 32 + j * 16,
                                    c[i][j], 128, wmma::mem_row_major);
    __syncthreads();

    // epilogue: scale by rsqrt(deg+1), pack fp16
    for (int i = tid; i < 64 * 32; i += 256) {
        int r = i >> 5, cc = i & 31;
        int gr = row0 + r;
        if (gr < N_NODES) {
            float d = rsqrtf((float)(g_counts[gr] + 1));
            float4 v = *(const float4*)(sm.c + r * 128 + cc * 4);
            h4 h;
            h.a = __floats2half2_rn(v.x * d, v.y * d);
            h.b = __floats2half2_rn(v.z * d, v.w * d);
            g_hs1[(size_t)gr * 32 + cc] = h;
        }
    }
}

// ---------------- GEMM layer 2 (tensor cores, A staged through smem) ----------------
// g_hs2[r] = fp16( (g_h1[r]@W2) * rsqrt(deg[r]+1) ). Block = 64 rows x 64 cols, 8 warps.
// A-tile (fp16, 64x128, stride-136 smem) is coalesced-copied then wmma-loaded from
// smem — no scattered/duplicated global fragment loads.
__global__ __launch_bounds__(256) void k_gemm2_tc() {
    __shared__ union SM2 {
        __half a[64 * 136];   // 17.4KB
        float  c[64 * 64];    // 16KB
    } sm;
    const int tid = threadIdx.x;
    const int wid = tid >> 5;
    const int row0 = blockIdx.x * 64;
    const int mi = wid >> 1;        // 0..3
    const int nj2 = wid & 1;        // 0..1

    // stage A tile: g_h1 (fp16) -> smem, coalesced h4 copies.
    // row0+r <= 781*64+63 = 50047 < N_NODES+PAD_ROWS -> always in-bounds;
    // pad rows are zero and their outputs are discarded.
    for (int i = tid; i < 64 * 32; i += 256) {
        int r = i >> 5, q = i & 31;
        h4 v = g_h1[(size_t)(row0 + r) * 32 + q];
        *(h4*)(sm.a + r * 136 + q * 4) = v;
    }
    __syncthreads();

    wmma::fragment<wmma::accumulator, 16, 16, 16, float> c[2];
#pragma unroll
    for (int j = 0; j < 2; j++) wmma::fill_fragment(c[j], 0.f);

    const __half* B = (const __half*)g_w2h;

    for (int k = 0; k < 128; k += 16) {
        wmma::fragment<wmma::matrix_a, 16, 16, 16, __half, wmma::row_major> a;
        wmma::load_matrix_sync(a, sm.a + mi * 16 * 136 + k, 136);
        wmma::fragment<wmma::matrix_b, 16, 16, 16, __half, wmma::row_major> b[2];
        wmma::load_matrix_sync(b[0], B + k * 64 + nj2 * 32 + 0, 64);
        wmma::load_matrix_sync(b[1], B + k * 64 + nj2 * 32 + 16, 64);
#pragma unroll
        for (int j = 0; j < 2; j++)
            wmma::mma_sync(c[j], a, b[j], c[j]);
    }
    __syncthreads();   // done reading sm.a before aliasing as sm.c

#pragma unroll
    for (int j = 0; j < 2; j++)
        wmma::store_matrix_sync(sm.c + mi * 16 * 64 + nj2 * 32 + j * 16,
                                c[j], 64, wmma::mem_row_major);
    __syncthreads();

    for (int i = tid; i < 64 * 32; i += 256) {
        int r = i >> 5, cc = i & 31;
        int gr = row0 + r;
        if (gr < N_NODES) {
            float d = rsqrtf((float)(g_counts[gr] + 1));
            float2 v = *(const float2*)(sm.c + r * 64 + cc * 2);
            g_hs2[(size_t)gr * 32 + cc] = __floats2half2_rn(v.x * d, v.y * d);
        }
    }
}

// ---------------- aggregation layer 1: 2 nodes per warp, h8 (16B) lanes ----------------
// Half-warp h owns node = 2*warp+h; lane covers 8 features via one LDG.128.
__global__ __launch_bounds__(256) void k_agg1(const float* __restrict__ bias) {
    __shared__ int sidx[8][32];
    int warp_g = (blockIdx.x * blockDim.x + threadIdx.x) >> 5;  // 0..24999
    int w = threadIdx.x >> 5;
    int lane = threadIdx.x & 31;
    int half = lane >> 4;
    int hl = lane & 15;
    int node = warp_g * 2 + half;            // exact: 3125 blocks * 16 nodes

    int cnt = g_counts[node];
    float d = rsqrtf((float)(cnt + 1));
    int e = min(cnt, BUCKET);
    const int* row = g_bucket + (size_t)node * BUCKET;
    const h8* hv = (const h8*)g_hs1;         // 16 h8 per 256B row

    // self loop (fp32)
    h8 sv = hv[node * 16 + hl];
    float2 fa = __half22float2(sv.a), fb = __half22float2(sv.b);
    float2 fc = __half22float2(sv.c), fd = __half22float2(sv.d);
    float acc[8] = {fa.x, fa.y, fb.x, fb.y, fc.x, fc.y, fd.x, fd.y};

    int eo = __shfl_xor_sync(0xffffffffu, e, 16);
    int emax = max(e, eo);

    for (int base = 0; base < emax; base += 16) {
        int idx = base + hl;
        sidx[w][lane] = (idx < e) ? row[idx] : N_NODES;   // sentinel = zero row
        __syncwarp();
#pragma unroll
        for (int j = 0; j < 16; j += 4) {
            int s0 = sidx[w][(half << 4) | (j + 0)];
            int s1 = sidx[w][(half << 4) | (j + 1)];
            int s2 = sidx[w][(half << 4) | (j + 2)];
            int s3 = sidx[w][(half << 4) | (j + 3)];
            h8 v0 = hv[s0 * 16 + hl];
            h8 v1 = hv[s1 * 16 + hl];
            h8 v2 = hv[s2 * 16 + hl];
            h8 v3 = hv[s3 * 16 + hl];
            __half2 ta = __hadd2(__hadd2(v0.a, v1.a), __hadd2(v2.a, v3.a));
            __half2 tb = __hadd2(__hadd2(v0.b, v1.b), __hadd2(v2.b, v3.b));
            __half2 tc = __hadd2(__hadd2(v0.c, v1.c), __hadd2(v2.c, v3.c));
            __half2 td = __hadd2(__hadd2(v0.d, v1.d), __hadd2(v2.d, v3.d));
            float2 g0 = __half22float2(ta), g1 = __half22float2(tb);
            float2 g2 = __half22float2(tc), g3 = __half22float2(td);
            acc[0] += g0.x; acc[1] += g0.y; acc[2] += g1.x; acc[3] += g1.y;
            acc[4] += g2.x; acc[5] += g2.y; acc[6] += g3.x; acc[7] += g3.y;
        }
        __syncwarp();
    }

    // bias: lane covers features hl*8 .. hl*8+7
    float4 b0 = ((const float4*)bias)[hl * 2 + 0];
    float4 b1 = ((const float4*)bias)[hl * 2 + 1];
    h8 o;
    o.a = __floats2half2_rn(fmaxf(acc[0] * d + b0.x, 0.f), fmaxf(acc[1] * d + b0.y, 0.f));
    o.b = __floats2half2_rn(fmaxf(acc[2] * d + b0.z, 0.f), fmaxf(acc[3] * d + b0.w, 0.f));
    o.c = __floats2half2_rn(fmaxf(acc[4] * d + b1.x, 0.f), fmaxf(acc[5] * d + b1.y, 0.f));
    o.d = __floats2half2_rn(fmaxf(acc[6] * d + b1.z, 0.f), fmaxf(acc[7] * d + b1.w, 0.f));
    ((h8*)g_h1)[node * 16 + hl] = o;
}

// ---------------- aggregation layer 2: 2 nodes per warp, h4 (8B) lanes ----------------
// Also self-cleans g_counts (last consumer) so next call starts from zeros.
__global__ __launch_bounds__(256) void k_agg2(const float* __restrict__ bias,
                                              float* __restrict__ out) {
    __shared__ int sidx[8][32];
    int warp_g = (blockIdx.x * blockDim.x + threadIdx.x) >> 5;
    int w = threadIdx.x >> 5;
    int lane = threadIdx.x & 31;
    int half = lane >> 4;
    int hl = lane & 15;
    int node = warp_g * 2 + half;

    int cnt = g_counts[node];
    float d = rsqrtf((float)(cnt + 1));
    int e = min(cnt, BUCKET);
    const int* row = g_bucket + (size_t)node * BUCKET;
    const h4* hv = (const h4*)g_hs2;         // 16 h4 per 128B row

    // self loop (fp32)
    h4 sv = hv[node * 16 + hl];
    float2 fa = __half22float2(sv.a), fb = __half22float2(sv.b);
    float acc[4] = {fa.x, fa.y, fb.x, fb.y};

    int eo = __shfl_xor_sync(0xffffffffu, e, 16);
    int emax = max(e, eo);

    for (int base = 0; base < emax; base += 16) {
        int idx = base + hl;
        sidx[w][lane] = (idx < e) ? row[idx] : N_NODES;   // sentinel = zero row
        __syncwarp();
#pragma unroll
        for (int j = 0; j < 16; j += 4) {
            int s0 = sidx[w][(half << 4) | (j + 0)];
            int s1 = sidx[w][(half << 4) | (j + 1)];
            int s2 = sidx[w][(half << 4) | (j + 2)];
            int s3 = sidx[w][(half << 4) | (j + 3)];
            h4 v0 = hv[s0 * 16 + hl];
            h4 v1 = hv[s1 * 16 + hl];
            h4 v2 = hv[s2 * 16 + hl];
            h4 v3 = hv[s3 * 16 + hl];
            __half2 ta = __hadd2(__hadd2(v0.a, v1.a), __hadd2(v2.a, v3.a));
            __half2 tb = __hadd2(__hadd2(v0.b, v1.b), __hadd2(v2.b, v3.b));
            float2 g0 = __half22float2(ta), g1 = __half22float2(tb);
            acc[0] += g0.x; acc[1] += g0.y; acc[2] += g1.x; acc[3] += g1.y;
        }
        __syncwarp();
    }

    // bias + output: lane covers cols hl*4 .. hl*4+3 (16B-aligned float4 store)
    float4 b = ((const float4*)bias)[hl];
    float4 o = make_float4(acc[0] * d + b.x, acc[1] * d + b.y,
                           acc[2] * d + b.z, acc[3] * d + b.w);
    ((float4*)out)[node * 16 + hl] = o;

    if (hl == 0) g_counts[node] = 0;         // self-clean for the next call
}

// ---------------- launch: kernel launches ONLY (5 launches) ----------------
extern "C" void kernel_launch(void* const* d_in, const int* in_sizes, int n_in,
                              void* d_out, int out_size) {
    const float* x = (const float*)d_in[0];
    const int* ei = (const int*)d_in[1];   // int32 [2, N_EDGES]
    const float* W1 = (const float*)d_in[2];
    const float* b1 = (const float*)d_in[3];
    const float* W2 = (const float*)d_in[4];
    const float* b2 = (const float*)d_in[5];
    float* out = (float*)d_out;

    const int* esrc = ei;
    const int* edst = ei + N_EDGES;

    k_fill<<<(N_EDGES + 255) / 256, 256>>>(esrc, edst, W1, W2);

    const int gemm_blocks = (N_NODES + 63) / 64;   // 782
    const int agg_blocks = N_NODES / 16;           // 3125 (16 nodes per block)

    // layer 1
    k_gemm1_tc<<<gemm_blocks, 256>>>(x);
    k_agg1<<<agg_blocks, 256>>>(b1);
    // layer 2
    k_gemm2_tc<<<gemm_blocks, 256>>>();
    k_agg2<<<agg_blocks, 256>>>(b2, out);
}